// round 10
// baseline (speedup 1.0000x reference)
#include <cuda_runtime.h>
#include <cuda_fp16.h>
#include <cstdint>

#define BH   32
#define S    2048
#define D    64
#define TQ   16
#define NT   512
#define SCP  2052            // fp32 score row stride (floats)
#define QSP  68
#define RMP  18
#define PSTR 1036            // p hi/lo row stride (u32 pairs)
#define NEG_INF_F (-1e10f)
#define SCALE     (0.125f)

// smem layout (u32 units)
#define OFF_P     0            // 33152 u32: fp32 scores, then p hi/lo overlay
#define OFF_PLO   16576
#define OFF_BUFA  33152        // tile buffer A (9216 u32)
#define OFF_BUFB  42368        // tile buffer B (9216 u32)
#define OFF_QS    51584        // 1088 floats
#define OFF_RMAX  52672        // 288 floats
#define OFF_INVS  52960        // 16 floats
#define SMEM_U32  52976
#define SMEM_BYTES (SMEM_U32 * 4)

// K tile: hi 128 rows x 36 u32 (stride), lo at +4608
#define KSTR 36
#define KLO  4608
// V^T tile: hi 64 rows x 68 u32, lo at +4352
#define VSTR 68
#define VLO  4352

// pre-split fp16 operands in global scratch
__device__ __half g_Khi[BH * S * D];
__device__ __half g_Klo[BH * S * D];
__device__ __half g_Vthi[BH * D * S];
__device__ __half g_Vtlo[BH * D * S];

__device__ __forceinline__ uint32_t pack_h2(float x, float y) {
    __half2 h = __floats2half2_rn(x, y);
    return *reinterpret_cast<uint32_t*>(&h);
}
__device__ __forceinline__ float2 unpack_h2(uint32_t u) {
    __half2 h = *reinterpret_cast<__half2*>(&u);
    return __half22float2(h);
}
__device__ __forceinline__ void split2(float x, float y, uint32_t& hi, uint32_t& lo) {
    hi = pack_h2(x, y);
    float2 hf = unpack_h2(hi);
    lo = pack_h2(x - hf.x, y - hf.y);
}

__device__ __forceinline__ void mma_f16(float* c, const uint32_t* a, uint32_t b0, uint32_t b1) {
    asm volatile(
        "mma.sync.aligned.m16n8k16.row.col.f32.f16.f16.f32 "
        "{%0,%1,%2,%3},{%4,%5,%6,%7},{%8,%9},{%0,%1,%2,%3};"
        : "+f"(c[0]), "+f"(c[1]), "+f"(c[2]), "+f"(c[3])
        : "r"(a[0]), "r"(a[1]), "r"(a[2]), "r"(a[3]), "r"(b0), "r"(b1));
}

__device__ __forceinline__ void cpa16(void* dst, const void* src) {
    uint32_t d = (uint32_t)__cvta_generic_to_shared(dst);
    asm volatile("cp.async.cg.shared.global [%0], [%1], 16;" :: "r"(d), "l"(src));
}
__device__ __forceinline__ void cp_commit() { asm volatile("cp.async.commit_group;"); }
__device__ __forceinline__ void cp_wait_all() { asm volatile("cp.async.wait_group 0;" ::: "memory"); }

// K tile p: 128 rows x 64 fp16, hi+lo
__device__ __forceinline__ void cp_ktile(const __half* khi, const __half* klo,
                                         uint32_t* buf, int t) {
    #pragma unroll
    for (int i = 0; i < 4; ++i) {
        int idx = t + i * NT;            // 0..2047
        int cidx = idx & 1023;
        int r = cidx >> 3, off = cidx & 7;
        const __half* src = ((idx < 1024) ? khi : klo) + r * 64 + off * 8;
        uint32_t* dst = buf + ((idx < 1024) ? 0 : KLO) + r * KSTR + off * 4;
        cpa16(dst, src);
    }
    cp_commit();
}

// V^T tile: 64 d-rows x 128 fp16 (cols pcol..pcol+127), hi+lo
__device__ __forceinline__ void cp_vtile(const __half* vhi, const __half* vlo,
                                         uint32_t* buf, int t, int pcol) {
    #pragma unroll
    for (int i = 0; i < 4; ++i) {
        int idx = t + i * NT;
        int cidx = idx & 1023;
        int r = cidx >> 4, off = cidx & 15;
        const __half* src = ((idx < 1024) ? vhi : vlo) + (size_t)r * S + pcol + off * 8;
        uint32_t* dst = buf + ((idx < 1024) ? 0 : VLO) + r * VSTR + off * 4;
        cpa16(dst, src);
    }
    cp_commit();
}

// ---------------- pre-kernels ----------------
__global__ void conv_k_kernel(const float* __restrict__ K) {
    int i = blockIdx.x * blockDim.x + threadIdx.x;
    float v = K[i];
    __half h = __float2half_rn(v);
    g_Khi[i] = h;
    g_Klo[i] = __float2half_rn(v - __half2float(h));
}

__global__ void conv_vt_kernel(const float* __restrict__ V) {
    __shared__ float tile[64][65];
    int bh = blockIdx.y, s0 = blockIdx.x * 64;
    int tid = threadIdx.x;
    #pragma unroll
    for (int i = 0; i < 16; ++i) {
        int r = i * 4 + (tid >> 6), d = tid & 63;
        tile[r][d] = V[((size_t)bh * S + s0 + r) * D + d];
    }
    __syncthreads();
    #pragma unroll
    for (int i = 0; i < 16; ++i) {
        int dr = i * 4 + (tid >> 6), sc_ = tid & 63;
        float v = tile[sc_][dr];
        __half h = __float2half_rn(v);
        size_t o = ((size_t)bh * D + dr) * S + s0 + sc_;
        g_Vthi[o] = h;
        g_Vtlo[o] = __float2half_rn(v - __half2float(h));
    }
}

// ---------------- main kernel ----------------
__global__ __launch_bounds__(NT, 1)
void dist_attn_kernel(const float* __restrict__ Q,
                      const float* __restrict__ dist,
                      const int* __restrict__ mask,
                      float* __restrict__ ctx,
                      float* __restrict__ attn)
{
    extern __shared__ uint32_t smu[];
    uint32_t* phi  = smu + OFF_P;
    uint32_t* plo  = smu + OFF_PLO;
    float*    sc   = (float*)(smu + OFF_P);     // fp32 scores (phase 1/2)
    uint32_t* bufA = smu + OFF_BUFA;
    uint32_t* bufB = smu + OFF_BUFB;
    float*    Qs   = (float*)(smu + OFF_QS);
    float*    rmax = (float*)(smu + OFF_RMAX);
    float*    invs = (float*)(smu + OFF_INVS);

    const int t    = threadIdx.x;
    const int warp = t >> 5;
    const int lane = t & 31;
    const int gid  = lane >> 2;
    const int tig  = lane & 3;
    const int bh = blockIdx.y;
    const int q0 = blockIdx.x * TQ;
    const size_t rowbase = (size_t)bh * S;

    const __half* Khi_b = g_Khi + (size_t)bh * S * D;
    const __half* Klo_b = g_Klo + (size_t)bh * S * D;

    // kick off K tile 0
    cp_ktile(Khi_b, Klo_b, bufA, t);

    if (t < 256) {
        const float4 v = ((const float4*)(Q + (rowbase + q0) * D))[t];
        int qr = t >> 4, d4 = t & 15;
        *(float4*)(Qs + qr * QSP + d4 * 4) = v;
    }
    __syncthreads();

    // Q A-fragments (fp16 hi/lo), 4 k16-chunks
    uint32_t qa_hi[4][4], qa_lo[4][4];
    #pragma unroll
    for (int c = 0; c < 4; ++c) {
        const float* qg  = Qs + gid * QSP       + c * 16 + 2 * tig;
        const float* qg8 = Qs + (gid + 8) * QSP + c * 16 + 2 * tig;
        split2(qg[0],  qg[1],  qa_hi[c][0], qa_lo[c][0]);
        split2(qg8[0], qg8[1], qa_hi[c][1], qa_lo[c][1]);
        split2(qg[8],  qg[9],  qa_hi[c][2], qa_lo[c][2]);
        split2(qg8[8], qg8[9], qa_hi[c][3], qa_lo[c][3]);
    }

    // ============ Phase 1: QK^T + dist/mask/scale + row-max ============
    const size_t rg0 = (rowbase + q0 + gid) * S;
    const size_t rg8 = (rowbase + q0 + gid + 8) * S;
    const int colw = warp * 8 + 2 * tig;

    float2 dd0[2], dd1[2];
    int2   mm0[2], mm1[2];
    #pragma unroll
    for (int p = 0; p < 2; ++p) {
        int col = p * 128 + colw;
        dd0[p] = *(const float2*)(dist + rg0 + col);
        dd1[p] = *(const float2*)(dist + rg8 + col);
        mm0[p] = *(const int2*)(mask + rg0 + col);
        mm1[p] = *(const int2*)(mask + rg8 + col);
    }

    float m0 = -3.4e38f, m1 = -3.4e38f;
    #pragma unroll
    for (int p = 0; p < 16; ++p) {
        uint32_t* cur = (p & 1) ? bufB : bufA;
        uint32_t* nxt = (p & 1) ? bufA : bufB;
        const int sl = p & 1;
        float2 d0 = dd0[sl], d1 = dd1[sl];
        int2   k0 = mm0[sl], k1 = mm1[sl];
        if (p + 2 < 16) {
            int col = (p + 2) * 128 + colw;
            dd0[sl] = *(const float2*)(dist + rg0 + col);
            dd1[sl] = *(const float2*)(dist + rg8 + col);
            mm0[sl] = *(const int2*)(mask + rg0 + col);
            mm1[sl] = *(const int2*)(mask + rg8 + col);
        }
        cp_wait_all();
        __syncthreads();
        if (p < 15) cp_ktile(Khi_b + (p + 1) * 128 * D, Klo_b + (p + 1) * 128 * D, nxt, t);

        float aHH[4] = {0,0,0,0}, aHL[4] = {0,0,0,0}, aLH[4] = {0,0,0,0};
        const uint32_t* kb = cur + (warp * 8 + gid) * KSTR + tig;
        #pragma unroll
        for (int c = 0; c < 4; ++c) {
            uint32_t b0h = kb[c * 8],       b1h = kb[c * 8 + 4];
            uint32_t b0l = kb[KLO + c * 8], b1l = kb[KLO + c * 8 + 4];
            mma_f16(aHH, qa_hi[c], b0h, b1h);
            mma_f16(aHL, qa_hi[c], b0l, b1l);
            mma_f16(aLH, qa_lo[c], b0h, b1h);
        }
        float s0 = aHH[0] + aHL[0] + aLH[0];
        float s1 = aHH[1] + aHL[1] + aLH[1];
        float s2 = aHH[2] + aHL[2] + aLH[2];
        float s3 = aHH[3] + aHL[3] + aLH[3];
        s0 = k0.x ? NEG_INF_F : d0.x * s0 * SCALE;
        s1 = k0.y ? NEG_INF_F : d0.y * s1 * SCALE;
        s2 = k1.x ? NEG_INF_F : d1.x * s2 * SCALE;
        s3 = k1.y ? NEG_INF_F : d1.y * s3 * SCALE;
        m0 = fmaxf(m0, fmaxf(s0, s1));
        m1 = fmaxf(m1, fmaxf(s2, s3));
        const int col = p * 128 + colw;
        *(float2*)(sc + gid * SCP + col)       = make_float2(s0, s1);
        *(float2*)(sc + (gid + 8) * SCP + col) = make_float2(s2, s3);
    }
    #pragma unroll
    for (int o = 1; o <= 2; o <<= 1) {
        m0 = fmaxf(m0, __shfl_xor_sync(0xffffffffu, m0, o));
        m1 = fmaxf(m1, __shfl_xor_sync(0xffffffffu, m1, o));
    }
    if (tig == 0) {
        rmax[warp * RMP + gid]     = m0;
        rmax[warp * RMP + gid + 8] = m1;
    }
    __syncthreads();

    // prefetch V^T tile 0 (overlaps softmax)
    const __half* Vthi_b = g_Vthi + (size_t)bh * D * S;
    const __half* Vtlo_b = g_Vtlo + (size_t)bh * D * S;
    cp_vtile(Vthi_b, Vtlo_b, bufA, t, 0);

    // ============ Phase 2: exp + row-sum, then store p as fp16 hi/lo ============
    {
        const int q = warp;
        float4* scRow = (float4*)(sc + q * SCP);

        float m = (lane < 16) ? rmax[lane * RMP + q] : -3.4e38f;
        #pragma unroll
        for (int o = 16; o > 0; o >>= 1)
            m = fmaxf(m, __shfl_xor_sync(0xffffffffu, m, o));

        float4 sv[16];
        float sum = 0.f;
        #pragma unroll
        for (int i = 0; i < 16; ++i) {
            float4 s = scRow[i * 32 + lane];
            s.x = __expf(s.x - m); s.y = __expf(s.y - m);
            s.z = __expf(s.z - m); s.w = __expf(s.w - m);
            sv[i] = s;
            sum += s.x + s.y + s.z + s.w;
        }
        #pragma unroll
        for (int o = 16; o > 0; o >>= 1)
            sum += __shfl_xor_sync(0xffffffffu, sum, o);
        if (lane == 0) invs[q] = 1.f / sum;

        __syncthreads();   // all fp32 reads done; safe to overlay hi/lo

        uint32_t* ph = phi + q * PSTR;
        uint32_t* pl = plo + q * PSTR;
        #pragma unroll
        for (int i = 0; i < 16; ++i) {
            float4 s = sv[i];
            uint32_t h0, l0, h1, l1;
            split2(s.x, s.y, h0, l0);
            split2(s.z, s.w, h1, l1);
            int pb = i * 64 + lane * 2;
            *(uint2*)(ph + pb) = make_uint2(h0, h1);
            *(uint2*)(pl + pb) = make_uint2(l0, l1);
        }
    }
    __syncthreads();

    // ============ Phase 3: context = p @ V (8-way split-k x 2-way n) + attn write ============
    {
        const int kg = warp & 7;    // k-group (16 rows per tile)
        const int nh = warp >> 3;   // d half
        const float invW = invs[warp];
        float4* attnRowW = (float4*)(attn + (rowbase + q0 + warp) * S);

        float acc[4][4];
        #pragma unroll
        for (int i = 0; i < 4; ++i)
            #pragma unroll
            for (int j = 0; j < 4; ++j) acc[i][j] = 0.f;

        #pragma unroll
        for (int p = 0; p < 16; ++p) {
            uint32_t* cur = (p & 1) ? bufB : bufA;
            uint32_t* nxt = (p & 1) ? bufA : bufB;
            cp_wait_all();
            __syncthreads();
            if (p < 15) cp_vtile(Vthi_b, Vtlo_b, nxt, t, (p + 1) * 128);

            // coalesced attn chunk: warp w writes row w, tile's 128 cols
            {
                int pb = p * 64 + lane * 2;
                uint2 h = *(const uint2*)(phi + warp * PSTR + pb);
                uint2 l = *(const uint2*)(plo + warp * PSTR + pb);
                float2 ha = unpack_h2(h.x), la = unpack_h2(l.x);
                float2 hb = unpack_h2(h.y), lb = unpack_h2(l.y);
                attnRowW[p * 32 + lane] = make_float4(
                    (ha.x + la.x) * invW, (ha.y + la.y) * invW,
                    (hb.x + lb.x) * invW, (hb.y + lb.y) * invW);
            }

            // A fragments from p hi/lo
            const int pb = p * 64 + kg * 8 + tig;
            uint32_t Ah[4], Al[4];
            Ah[0] = phi[gid * PSTR + pb];
            Ah[1] = phi[(gid + 8) * PSTR + pb];
            Ah[2] = phi[gid * PSTR + pb + 4];
            Ah[3] = phi[(gid + 8) * PSTR + pb + 4];
            Al[0] = plo[gid * PSTR + pb];
            Al[1] = plo[(gid + 8) * PSTR + pb];
            Al[2] = plo[gid * PSTR + pb + 4];
            Al[3] = plo[(gid + 8) * PSTR + pb + 4];

            #pragma unroll
            for (int nt = 0; nt < 4; ++nt) {
                const uint32_t* r = cur + (nh * 32 + nt * 8 + gid) * VSTR + kg * 8 + tig;
                uint32_t b0h = r[0],   b1h = r[4];
                uint32_t b0l = r[VLO], b1l = r[VLO + 4];
                mma_f16(acc[nt], Ah, b0h, b1h);
                mma_f16(acc[nt], Ah, b0l, b1l);
                mma_f16(acc[nt], Al, b0h, b1h);
            }
        }
        __syncthreads();

        // split-k reduce: red[kg 8][q 16][68]
        float* red = (float*)bufA;
        #pragma unroll
        for (int nt = 0; nt < 4; ++nt) {
            int d = nh * 32 + nt * 8 + 2 * tig;
            *(float2*)(red + kg * 1088 + gid * 68 + d) =
                make_float2(acc[nt][0], acc[nt][1]);
            *(float2*)(red + kg * 1088 + (gid + 8) * 68 + d) =
                make_float2(acc[nt][2], acc[nt][3]);
        }
        __syncthreads();

        #pragma unroll
        for (int o = t; o < TQ * D; o += NT) {
            int q = o >> 6, d = o & 63;
            float s = 0.f;
            #pragma unroll
            for (int g = 0; g < 8; ++g)
                s += red[g * 1088 + q * 68 + d];
            ctx[(rowbase + q0 + q) * D + d] = s * invs[q];
        }
    }
}

extern "C" void kernel_launch(void* const* d_in, const int* in_sizes, int n_in,
                              void* d_out, int out_size)
{
    const float* Q    = (const float*)d_in[0];
    const float* K    = (const float*)d_in[1];
    const float* V    = (const float*)d_in[2];
    const float* dist = (const float*)d_in[3];
    const int*   mask = (const int*)d_in[4];

    float* ctx  = (float*)d_out;
    float* attn = (float*)d_out + (size_t)BH * S * D;

    // pre-split K and V (V transposed) into fp16 hi/lo
    conv_k_kernel<<<(BH * S * D) / 256, 256>>>(K);
    {
        dim3 g(S / 64, BH);
        conv_vt_kernel<<<g, 256>>>(V);
    }

    cudaFuncSetAttribute(dist_attn_kernel,
                         cudaFuncAttributeMaxDynamicSharedMemorySize,
                         SMEM_BYTES);

    dim3 grid(S / TQ, BH);
    dist_attn_kernel<<<grid, NT, SMEM_BYTES>>>(Q, dist, mask, ctx, attn);
}

// round 11
// speedup vs baseline: 1.0035x; 1.0035x over previous
#include <cuda_runtime.h>
#include <cuda_fp16.h>
#include <cstdint>

#define BH   32
#define S    2048
#define D    64
#define TQ   16
#define NT   512
#define SCP  2052            // fp32 score row stride (floats)
#define QSP  68
#define RMP  18
#define PSTR 1036            // p hi/lo row stride (u32 pairs)
#define NEG_INF_F (-1e10f)
#define SCALE     (0.125f)

// smem layout (u32 units)
#define OFF_P     0            // 33152 u32: fp32 scores, then p hi/lo overlay
#define OFF_PLO   16576
#define OFF_BUFA  33152        // tile buffer A (9216 u32)
#define OFF_BUFB  42368        // tile buffer B (9216 u32)
#define OFF_QS    51584        // 1088 floats
#define OFF_RMAX  52672        // 288 floats
#define OFF_INVS  52960        // 16 floats
#define SMEM_U32  52976
#define SMEM_BYTES (SMEM_U32 * 4)

// K tile: hi 128 rows x 36 u32 (stride), lo at +4608
#define KSTR 36
#define KLO  4608
// V^T tile: hi 64 rows x 68 u32, lo at +4352
#define VSTR 68
#define VLO  4352

// pre-split fp16 operands in global scratch
__device__ __half g_Khi[BH * S * D];
__device__ __half g_Klo[BH * S * D];
__device__ __half g_Vthi[BH * D * S];
__device__ __half g_Vtlo[BH * D * S];

__device__ __forceinline__ uint32_t pack_h2(float x, float y) {
    __half2 h = __floats2half2_rn(x, y);
    return *reinterpret_cast<uint32_t*>(&h);
}
__device__ __forceinline__ float2 unpack_h2(uint32_t u) {
    __half2 h = *reinterpret_cast<__half2*>(&u);
    return __half22float2(h);
}
__device__ __forceinline__ void split2(float x, float y, uint32_t& hi, uint32_t& lo) {
    hi = pack_h2(x, y);
    float2 hf = unpack_h2(hi);
    lo = pack_h2(x - hf.x, y - hf.y);
}

__device__ __forceinline__ void mma_f16(float* c, const uint32_t* a, uint32_t b0, uint32_t b1) {
    asm volatile(
        "mma.sync.aligned.m16n8k16.row.col.f32.f16.f16.f32 "
        "{%0,%1,%2,%3},{%4,%5,%6,%7},{%8,%9},{%0,%1,%2,%3};"
        : "+f"(c[0]), "+f"(c[1]), "+f"(c[2]), "+f"(c[3])
        : "r"(a[0]), "r"(a[1]), "r"(a[2]), "r"(a[3]), "r"(b0), "r"(b1));
}

__device__ __forceinline__ void cpa16(void* dst, const void* src) {
    uint32_t d = (uint32_t)__cvta_generic_to_shared(dst);
    asm volatile("cp.async.cg.shared.global [%0], [%1], 16;" :: "r"(d), "l"(src));
}
__device__ __forceinline__ void cp_commit() { asm volatile("cp.async.commit_group;"); }
__device__ __forceinline__ void cp_wait_all() { asm volatile("cp.async.wait_group 0;" ::: "memory"); }

// K tile p: 128 rows x 64 fp16, hi+lo
__device__ __forceinline__ void cp_ktile(const __half* khi, const __half* klo,
                                         uint32_t* buf, int t) {
    #pragma unroll
    for (int i = 0; i < 4; ++i) {
        int idx = t + i * NT;            // 0..2047
        int cidx = idx & 1023;
        int r = cidx >> 3, off = cidx & 7;
        const __half* src = ((idx < 1024) ? khi : klo) + r * 64 + off * 8;
        uint32_t* dst = buf + ((idx < 1024) ? 0 : KLO) + r * KSTR + off * 4;
        cpa16(dst, src);
    }
    cp_commit();
}

// V^T tile: 64 d-rows x 128 fp16 (cols pcol..pcol+127), hi+lo
__device__ __forceinline__ void cp_vtile(const __half* vhi, const __half* vlo,
                                         uint32_t* buf, int t, int pcol) {
    #pragma unroll
    for (int i = 0; i < 4; ++i) {
        int idx = t + i * NT;
        int cidx = idx & 1023;
        int r = cidx >> 4, off = cidx & 15;
        const __half* src = ((idx < 1024) ? vhi : vlo) + (size_t)r * S + pcol + off * 8;
        uint32_t* dst = buf + ((idx < 1024) ? 0 : VLO) + r * VSTR + off * 4;
        cpa16(dst, src);
    }
    cp_commit();
}

// ---------------- pre-kernels ----------------
__global__ void conv_k_kernel(const float* __restrict__ K) {
    int i = blockIdx.x * blockDim.x + threadIdx.x;
    float v = K[i];
    __half h = __float2half_rn(v);
    g_Khi[i] = h;
    g_Klo[i] = __float2half_rn(v - __half2float(h));
}

__global__ void conv_vt_kernel(const float* __restrict__ V) {
    __shared__ float tile[64][65];
    int bh = blockIdx.y, s0 = blockIdx.x * 64;
    int tid = threadIdx.x;
    #pragma unroll
    for (int i = 0; i < 16; ++i) {
        int r = i * 4 + (tid >> 6), d = tid & 63;
        tile[r][d] = V[((size_t)bh * S + s0 + r) * D + d];
    }
    __syncthreads();
    #pragma unroll
    for (int i = 0; i < 16; ++i) {
        int dr = i * 4 + (tid >> 6), sc_ = tid & 63;
        float v = tile[sc_][dr];
        __half h = __float2half_rn(v);
        size_t o = ((size_t)bh * D + dr) * S + s0 + sc_;
        g_Vthi[o] = h;
        g_Vtlo[o] = __float2half_rn(v - __half2float(h));
    }
}

// ---------------- main kernel ----------------
__global__ __launch_bounds__(NT, 1)
void dist_attn_kernel(const float* __restrict__ Q,
                      const float* __restrict__ dist,
                      const int* __restrict__ mask,
                      float* __restrict__ ctx,
                      float* __restrict__ attn)
{
    extern __shared__ uint32_t smu[];
    uint32_t* phi  = smu + OFF_P;
    uint32_t* plo  = smu + OFF_PLO;
    float*    sc   = (float*)(smu + OFF_P);     // fp32 scores (phase 1/2)
    uint32_t* bufA = smu + OFF_BUFA;
    uint32_t* bufB = smu + OFF_BUFB;
    float*    Qs   = (float*)(smu + OFF_QS);
    float*    rmax = (float*)(smu + OFF_RMAX);
    float*    invs = (float*)(smu + OFF_INVS);

    const int t    = threadIdx.x;
    const int warp = t >> 5;
    const int lane = t & 31;
    const int gid  = lane >> 2;
    const int tig  = lane & 3;
    const int bh = blockIdx.y;
    const int q0 = blockIdx.x * TQ;
    const size_t rowbase = (size_t)bh * S;

    const __half* Khi_b = g_Khi + (size_t)bh * S * D;
    const __half* Klo_b = g_Klo + (size_t)bh * S * D;

    // kick off K tile 0
    cp_ktile(Khi_b, Klo_b, bufA, t);

    if (t < 256) {
        const float4 v = ((const float4*)(Q + (rowbase + q0) * D))[t];
        int qr = t >> 4, d4 = t & 15;
        *(float4*)(Qs + qr * QSP + d4 * 4) = v;
    }
    __syncthreads();

    // Q A-fragments (fp16 hi/lo), 4 k16-chunks
    uint32_t qa_hi[4][4], qa_lo[4][4];
    #pragma unroll
    for (int c = 0; c < 4; ++c) {
        const float* qg  = Qs + gid * QSP       + c * 16 + 2 * tig;
        const float* qg8 = Qs + (gid + 8) * QSP + c * 16 + 2 * tig;
        split2(qg[0],  qg[1],  qa_hi[c][0], qa_lo[c][0]);
        split2(qg8[0], qg8[1], qa_hi[c][1], qa_lo[c][1]);
        split2(qg[8],  qg[9],  qa_hi[c][2], qa_lo[c][2]);
        split2(qg8[8], qg8[9], qa_hi[c][3], qa_lo[c][3]);
    }

    // ============ Phase 1: QK^T + dist/mask/scale + row-max ============
    const size_t rg0 = (rowbase + q0 + gid) * S;
    const size_t rg8 = (rowbase + q0 + gid + 8) * S;
    const int colw = warp * 8 + 2 * tig;

    float2 dd0[2], dd1[2];
    int2   mm0[2], mm1[2];
    #pragma unroll
    for (int p = 0; p < 2; ++p) {
        int col = p * 128 + colw;
        dd0[p] = *(const float2*)(dist + rg0 + col);
        dd1[p] = *(const float2*)(dist + rg8 + col);
        mm0[p] = *(const int2*)(mask + rg0 + col);
        mm1[p] = *(const int2*)(mask + rg8 + col);
    }

    float m0 = -3.4e38f, m1 = -3.4e38f;
    #pragma unroll
    for (int p = 0; p < 16; ++p) {
        uint32_t* cur = (p & 1) ? bufB : bufA;
        uint32_t* nxt = (p & 1) ? bufA : bufB;
        const int sl = p & 1;
        float2 d0 = dd0[sl], d1 = dd1[sl];
        int2   k0 = mm0[sl], k1 = mm1[sl];
        if (p + 2 < 16) {
            int col = (p + 2) * 128 + colw;
            dd0[sl] = *(const float2*)(dist + rg0 + col);
            dd1[sl] = *(const float2*)(dist + rg8 + col);
            mm0[sl] = *(const int2*)(mask + rg0 + col);
            mm1[sl] = *(const int2*)(mask + rg8 + col);
        }
        cp_wait_all();
        __syncthreads();
        if (p < 15) cp_ktile(Khi_b + (p + 1) * 128 * D, Klo_b + (p + 1) * 128 * D, nxt, t);

        float aHH[4] = {0,0,0,0}, aHL[4] = {0,0,0,0}, aLH[4] = {0,0,0,0};
        const uint32_t* kb = cur + (warp * 8 + gid) * KSTR + tig;
        #pragma unroll
        for (int c = 0; c < 4; ++c) {
            uint32_t b0h = kb[c * 8],       b1h = kb[c * 8 + 4];
            uint32_t b0l = kb[KLO + c * 8], b1l = kb[KLO + c * 8 + 4];
            mma_f16(aHH, qa_hi[c], b0h, b1h);
            mma_f16(aHL, qa_hi[c], b0l, b1l);
            mma_f16(aLH, qa_lo[c], b0h, b1h);
        }
        float s0 = aHH[0] + aHL[0] + aLH[0];
        float s1 = aHH[1] + aHL[1] + aLH[1];
        float s2 = aHH[2] + aHL[2] + aLH[2];
        float s3 = aHH[3] + aHL[3] + aLH[3];
        s0 = k0.x ? NEG_INF_F : d0.x * s0 * SCALE;
        s1 = k0.y ? NEG_INF_F : d0.y * s1 * SCALE;
        s2 = k1.x ? NEG_INF_F : d1.x * s2 * SCALE;
        s3 = k1.y ? NEG_INF_F : d1.y * s3 * SCALE;
        m0 = fmaxf(m0, fmaxf(s0, s1));
        m1 = fmaxf(m1, fmaxf(s2, s3));
        const int col = p * 128 + colw;
        *(float2*)(sc + gid * SCP + col)       = make_float2(s0, s1);
        *(float2*)(sc + (gid + 8) * SCP + col) = make_float2(s2, s3);
    }
    #pragma unroll
    for (int o = 1; o <= 2; o <<= 1) {
        m0 = fmaxf(m0, __shfl_xor_sync(0xffffffffu, m0, o));
        m1 = fmaxf(m1, __shfl_xor_sync(0xffffffffu, m1, o));
    }
    if (tig == 0) {
        rmax[warp * RMP + gid]     = m0;
        rmax[warp * RMP + gid + 8] = m1;
    }
    __syncthreads();

    // prefetch V^T tile 0 (overlaps softmax)
    const __half* Vthi_b = g_Vthi + (size_t)bh * D * S;
    const __half* Vtlo_b = g_Vtlo + (size_t)bh * D * S;
    cp_vtile(Vthi_b, Vtlo_b, bufA, t, 0);

    // ============ Phase 2: exp + row-sum, then store p as fp16 hi/lo ============
    {
        const int q = warp;
        float4* scRow = (float4*)(sc + q * SCP);

        float m = (lane < 16) ? rmax[lane * RMP + q] : -3.4e38f;
        #pragma unroll
        for (int o = 16; o > 0; o >>= 1)
            m = fmaxf(m, __shfl_xor_sync(0xffffffffu, m, o));

        float4 sv[16];
        float sum = 0.f;
        #pragma unroll
        for (int i = 0; i < 16; ++i) {
            float4 s = scRow[i * 32 + lane];
            s.x = __expf(s.x - m); s.y = __expf(s.y - m);
            s.z = __expf(s.z - m); s.w = __expf(s.w - m);
            sv[i] = s;
            sum += s.x + s.y + s.z + s.w;
        }
        #pragma unroll
        for (int o = 16; o > 0; o >>= 1)
            sum += __shfl_xor_sync(0xffffffffu, sum, o);
        if (lane == 0) invs[q] = 1.f / sum;

        __syncthreads();   // all fp32 reads done; safe to overlay hi/lo

        uint32_t* ph = phi + q * PSTR;
        uint32_t* pl = plo + q * PSTR;
        #pragma unroll
        for (int i = 0; i < 16; ++i) {
            float4 s = sv[i];
            uint32_t h0, l0, h1, l1;
            split2(s.x, s.y, h0, l0);
            split2(s.z, s.w, h1, l1);
            int pb = i * 64 + lane * 2;
            *(uint2*)(ph + pb) = make_uint2(h0, h1);
            *(uint2*)(pl + pb) = make_uint2(l0, l1);
        }
    }
    __syncthreads();

    // ============ Phase 3: context = p @ V (8-way split-k x 2-way n) + attn write ============
    {
        const int kg = warp & 7;    // k-group (16 rows per tile)
        const int nh = warp >> 3;   // d half
        const float invW = invs[warp];
        float4* attnRowW = (float4*)(attn + (rowbase + q0 + warp) * S);

        float acc[4][4];
        #pragma unroll
        for (int i = 0; i < 4; ++i)
            #pragma unroll
            for (int j = 0; j < 4; ++j) acc[i][j] = 0.f;

        #pragma unroll
        for (int p = 0; p < 16; ++p) {
            uint32_t* cur = (p & 1) ? bufB : bufA;
            uint32_t* nxt = (p & 1) ? bufA : bufB;
            cp_wait_all();
            __syncthreads();
            if (p < 15) cp_vtile(Vthi_b, Vtlo_b, nxt, t, (p + 1) * 128);

            // coalesced attn chunk: warp w writes row w, tile's 128 cols
            {
                int pb = p * 64 + lane * 2;
                uint2 h = *(const uint2*)(phi + warp * PSTR + pb);
                uint2 l = *(const uint2*)(plo + warp * PSTR + pb);
                float2 ha = unpack_h2(h.x), la = unpack_h2(l.x);
                float2 hb = unpack_h2(h.y), lb = unpack_h2(l.y);
                attnRowW[p * 32 + lane] = make_float4(
                    (ha.x + la.x) * invW, (ha.y + la.y) * invW,
                    (hb.x + lb.x) * invW, (hb.y + lb.y) * invW);
            }

            // A fragments from p hi/lo
            const int pb = p * 64 + kg * 8 + tig;
            uint32_t Ah[4], Al[4];
            Ah[0] = phi[gid * PSTR + pb];
            Ah[1] = phi[(gid + 8) * PSTR + pb];
            Ah[2] = phi[gid * PSTR + pb + 4];
            Ah[3] = phi[(gid + 8) * PSTR + pb + 4];
            Al[0] = plo[gid * PSTR + pb];
            Al[1] = plo[(gid + 8) * PSTR + pb];
            Al[2] = plo[gid * PSTR + pb + 4];
            Al[3] = plo[(gid + 8) * PSTR + pb + 4];

            #pragma unroll
            for (int nt = 0; nt < 4; ++nt) {
                const uint32_t* r = cur + (nh * 32 + nt * 8 + gid) * VSTR + kg * 8 + tig;
                uint32_t b0h = r[0],   b1h = r[4];
                uint32_t b0l = r[VLO], b1l = r[VLO + 4];
                mma_f16(acc[nt], Ah, b0h, b1h);
                mma_f16(acc[nt], Ah, b0l, b1l);
                mma_f16(acc[nt], Al, b0h, b1h);
            }
        }
        __syncthreads();

        // split-k reduce: red[kg 8][q 16][68]
        float* red = (float*)bufA;
        #pragma unroll
        for (int nt = 0; nt < 4; ++nt) {
            int d = nh * 32 + nt * 8 + 2 * tig;
            *(float2*)(red + kg * 1088 + gid * 68 + d) =
                make_float2(acc[nt][0], acc[nt][1]);
            *(float2*)(red + kg * 1088 + (gid + 8) * 68 + d) =
                make_float2(acc[nt][2], acc[nt][3]);
        }
        __syncthreads();

        #pragma unroll
        for (int o = t; o < TQ * D; o += NT) {
            int q = o >> 6, d = o & 63;
            float s = 0.f;
            #pragma unroll
            for (int g = 0; g < 8; ++g)
                s += red[g * 1088 + q * 68 + d];
            ctx[(rowbase + q0 + q) * D + d] = s * invs[q];
        }
    }
}

extern "C" void kernel_launch(void* const* d_in, const int* in_sizes, int n_in,
                              void* d_out, int out_size)
{
    const float* Q    = (const float*)d_in[0];
    const float* K    = (const float*)d_in[1];
    const float* V    = (const float*)d_in[2];
    const float* dist = (const float*)d_in[3];
    const int*   mask = (const int*)d_in[4];

    float* ctx  = (float*)d_out;
    float* attn = (float*)d_out + (size_t)BH * S * D;

    // pre-split K and V (V transposed) into fp16 hi/lo
    conv_k_kernel<<<(BH * S * D) / 256, 256>>>(K);
    {
        dim3 g(S / 64, BH);
        conv_vt_kernel<<<g, 256>>>(V);
    }

    cudaFuncSetAttribute(dist_attn_kernel,
                         cudaFuncAttributeMaxDynamicSharedMemorySize,
                         SMEM_BYTES);

    dim3 grid(S / TQ, BH);
    dist_attn_kernel<<<grid, NT, SMEM_BYTES>>>(Q, dist, mask, ctx, attn);
}